// round 13
// baseline (speedup 1.0000x reference)
#include <cuda_runtime.h>

// SMFNet B=2,N=8192,D=64,DV=64,M=3 — chord mask = diag + superdiag(wrap).
// out[i] = w0 V0[i] + w1 V0[i+1] + w2 V0[i+2] + w3 V0[i+3]   (wrap)
//   V0 = X@Wg + bg
//   Am_j = X[j]·Wf[m][:,j] + bf[m][j],  Cm_j = X[j]·Wf[m][:,j+1] + bf[m][j+1]
// R13: CTA-level specialization. K1 = 128 AC-CTAs (latency-bound, coalesced
// Wf columns, column-shared A/C) + 128 GEMM-CTAs (issue-bound FFMA2), mixed
// on the SMs with no coupling barriers. K2 = streaming 4-tap combine.

#define Nc   8192
#define Dc   64
typedef unsigned long long u64;

// ---------------- scratch ----------------
__device__ float g_V0[2 * Nc * Dc];          // 4 MB
__device__ float g_A[2][3][Nc];
__device__ float g_C[2][3][Nc];

__device__ __forceinline__ u64 pack2(float x, float y) {
    u64 r;
    asm("mov.b64 %0, {%1, %2};" : "=l"(r) : "f"(x), "f"(y));
    return r;
}
__device__ __forceinline__ void fma2(u64& d, u64 a, u64 b) {
    asm("fma.rn.f32x2 %0, %1, %2, %3;" : "=l"(d) : "l"(a), "l"(b), "l"(d));
}

// ================= K1: AC CTAs (bid<128) + GEMM CTAs (bid>=128) =================
// GEMM smem: Xs 128*68*4 = 34816 B + Wgs 16384 B = 51200 B
// AC smem:   Xa 129*67*4 = 34572 B   (fits inside the same allocation)
#define K1_SMEM_BYTES 51200
#define GPAD 68
#define APAD 67

__global__ __launch_bounds__(256, 3)
void smf_k1(const float* __restrict__ X,
            const float* __restrict__ Wg,
            const float* __restrict__ bg,
            const float* __restrict__ Wf,
            const float* __restrict__ bf)
{
    extern __shared__ float sm[];
    const int t   = threadIdx.x;
    const int bid = blockIdx.x;

    if (bid < 128) {
        // ---------- AC CTA: 128 Wf columns, one batch, all 3 m ----------
        const int b  = bid >> 6;
        const int c0 = (bid & 63) * 128;
        float* Xa = sm;                       // [129][APAD]

        // stage X rows gi = (c0-1+jj) & 8191, jj=0..128 (scalar, coalesced)
        const float* Xb = X + (size_t)b * Nc * Dc;
        for (int idx = t; idx < 129 * 64; idx += 256) {
            int jj = idx >> 6, d = idx & 63;
            int gi = (c0 - 1 + jj) & (Nc - 1);
            Xa[jj * APAD + d] = __ldg(Xb + gi * 64 + d);
        }
        __syncthreads();

        const int c    = t & 127;
        const int half = t >> 7;               // 0: m=0,1 ; 1: m=2
        const int gi   = c0 + c;
        const int gim1 = (gi + Nc - 1) & (Nc - 1);
        const float* xa = &Xa[(c + 1) * APAD]; // X[gi]
        const float* xc = &Xa[c * APAD];       // X[gi-1]

        if (half == 0) {
            const float* w0p = Wf + gi;                      // m=0
            const float* w1p = Wf + (size_t)Dc * Nc + gi;    // m=1
            float A0a = 0.f, A0b = 0.f, C0a = 0.f, C0b = 0.f;
            float A1a = 0.f, A1b = 0.f, C1a = 0.f, C1b = 0.f;
            #pragma unroll 16
            for (int d = 0; d < Dc; d += 2) {
                float w00 = __ldg(w0p + (size_t)d * Nc);
                float w01 = __ldg(w0p + (size_t)(d + 1) * Nc);
                float w10 = __ldg(w1p + (size_t)d * Nc);
                float w11 = __ldg(w1p + (size_t)(d + 1) * Nc);
                float xA0 = xa[d], xA1 = xa[d + 1];
                float xC0 = xc[d], xC1 = xc[d + 1];
                A0a = fmaf(xA0, w00, A0a);  A0b = fmaf(xA1, w01, A0b);
                C0a = fmaf(xC0, w00, C0a);  C0b = fmaf(xC1, w01, C0b);
                A1a = fmaf(xA0, w10, A1a);  A1b = fmaf(xA1, w11, A1b);
                C1a = fmaf(xC0, w10, C1a);  C1b = fmaf(xC1, w11, C1b);
            }
            float bf0 = __ldg(bf + gi);
            float bf1 = __ldg(bf + Nc + gi);
            g_A[b][0][gi]   = A0a + A0b + bf0;
            g_C[b][0][gim1] = C0a + C0b + bf0;
            g_A[b][1][gi]   = A1a + A1b + bf1;
            g_C[b][1][gim1] = C1a + C1b + bf1;
        } else {
            const float* w2p = Wf + (size_t)2 * Dc * Nc + gi;
            float Aa = 0.f, Ab = 0.f, Ca = 0.f, Cb = 0.f;
            #pragma unroll 16
            for (int d = 0; d < Dc; d += 2) {
                float w20 = __ldg(w2p + (size_t)d * Nc);
                float w21 = __ldg(w2p + (size_t)(d + 1) * Nc);
                Aa = fmaf(xa[d],     w20, Aa);
                Ab = fmaf(xa[d + 1], w21, Ab);
                Ca = fmaf(xc[d],     w20, Ca);
                Cb = fmaf(xc[d + 1], w21, Cb);
            }
            float bf2 = __ldg(bf + 2 * Nc + gi);
            g_A[b][2][gi]   = Aa + Ab + bf2;
            g_C[b][2][gim1] = Ca + Cb + bf2;
        }
    } else {
        // ---------- GEMM CTA: 128 rows of V0 = X@Wg + bg ----------
        const int gid = bid - 128;
        const int b   = gid >> 6;
        const int r0  = (gid & 63) * 128;
        float* Xs  = sm;                       // [128][GPAD]
        float* Wgs = sm + 128 * GPAD;          // [64][64]

        const float4* Xb4 = reinterpret_cast<const float4*>(
            X + ((size_t)b * Nc + r0) * Dc);
        #pragma unroll
        for (int idx = t; idx < 128 * 16; idx += 256) {
            int row = idx >> 4, q = idx & 15;
            *reinterpret_cast<float4*>(&Xs[row * GPAD + q * 4]) = __ldg(Xb4 + idx);
        }
        const float4* Wg4 = reinterpret_cast<const float4*>(Wg);
        #pragma unroll
        for (int idx = t; idx < 64 * 16; idx += 256)
            *reinterpret_cast<float4*>(&Wgs[idx * 4]) = __ldg(Wg4 + idx);
        __syncthreads();

        const int rg = t >> 3;                 // 0..31 ; rows rg+32k
        const int cg = t & 7;                  // cols [8cg, 8cg+8)
        const int e0 = cg * 8;

        float4 bq0 = __ldg(reinterpret_cast<const float4*>(bg + e0));
        float4 bq1 = __ldg(reinterpret_cast<const float4*>(bg + e0 + 4));
        u64 bi0 = pack2(bq0.x, bq0.y), bi1 = pack2(bq0.z, bq0.w);
        u64 bi2 = pack2(bq1.x, bq1.y), bi3 = pack2(bq1.z, bq1.w);
        u64 acc[4][4];
        #pragma unroll
        for (int r = 0; r < 4; r++) {
            acc[r][0] = bi0; acc[r][1] = bi1; acc[r][2] = bi2; acc[r][3] = bi3;
        }

        const float* x0 = &Xs[ rg       * GPAD];
        const float* x1 = &Xs[(rg + 32) * GPAD];
        const float* x2 = &Xs[(rg + 64) * GPAD];
        const float* x3 = &Xs[(rg + 96) * GPAD];
        const float* wp = &Wgs[e0];

        #pragma unroll 8
        for (int d = 0; d < Dc; d++) {
            ulonglong2 wA = *reinterpret_cast<const ulonglong2*>(wp + d * 64);
            ulonglong2 wB = *reinterpret_cast<const ulonglong2*>(wp + d * 64 + 4);
            u64 xx0 = pack2(x0[d], x0[d]);
            fma2(acc[0][0], xx0, wA.x);  fma2(acc[0][1], xx0, wA.y);
            fma2(acc[0][2], xx0, wB.x);  fma2(acc[0][3], xx0, wB.y);
            u64 xx1 = pack2(x1[d], x1[d]);
            fma2(acc[1][0], xx1, wA.x);  fma2(acc[1][1], xx1, wA.y);
            fma2(acc[1][2], xx1, wB.x);  fma2(acc[1][3], xx1, wB.y);
            u64 xx2 = pack2(x2[d], x2[d]);
            fma2(acc[2][0], xx2, wA.x);  fma2(acc[2][1], xx2, wA.y);
            fma2(acc[2][2], xx2, wB.x);  fma2(acc[2][3], xx2, wB.y);
            u64 xx3 = pack2(x3[d], x3[d]);
            fma2(acc[3][0], xx3, wA.x);  fma2(acc[3][1], xx3, wA.y);
            fma2(acc[3][2], xx3, wB.x);  fma2(acc[3][3], xx3, wB.y);
        }
        #pragma unroll
        for (int r = 0; r < 4; r++) {
            const int row = rg + 32 * r;
            u64* dst = reinterpret_cast<u64*>(
                g_V0 + ((size_t)b * Nc + r0 + row) * 64 + e0);
            dst[0] = acc[r][0];  dst[1] = acc[r][1];
            dst[2] = acc[r][2];  dst[3] = acc[r][3];
        }
    }
}

// ================= K2: weights + 4-tap combine =================
__global__ __launch_bounds__(256, 8)
void smf_k2(float* __restrict__ out)
{
    __shared__ float Ws[64 * 4];
    const int t  = threadIdx.x;
    const int b  = blockIdx.y;
    const int r0 = blockIdx.x * 64;

    if (t < 64) {
        const int i  = r0 + t;
        const int i1 = (i + 1) & (Nc - 1);
        const int i2 = (i + 2) & (Nc - 1);
        float A1i = g_A[b][0][i], A1i1 = g_A[b][0][i1], A1i2 = g_A[b][0][i2];
        float C1i = g_C[b][0][i], C1i1 = g_C[b][0][i1], C1i2 = g_C[b][0][i2];
        float A2i = g_A[b][1][i], A2i1 = g_A[b][1][i1];
        float C2i = g_C[b][1][i], C2i1 = g_C[b][1][i1];
        float A3  = g_A[b][2][i], C3   = g_C[b][2][i];
        Ws[t * 4 + 0] = A3 * A2i * A1i;
        Ws[t * 4 + 1] = A3 * (A2i * C1i + C2i * A1i1) + C3 * A2i1 * A1i1;
        Ws[t * 4 + 2] = A3 * C2i * C1i1 + C3 * (A2i1 * C1i1 + C2i1 * A1i2);
        Ws[t * 4 + 3] = C3 * C2i1 * C1i2;
    }
    __syncthreads();

    #pragma unroll
    for (int k = 0; k < 4; k++) {
        const int task = t + k * 256;
        const int jr = task >> 4;
        const int e0 = (task & 15) * 4;
        const int i  = r0 + jr;
        const float* vbase = g_V0 + (size_t)b * Nc * 64;

        float4 p0 = *reinterpret_cast<const float4*>(vbase + (size_t)i * 64 + e0);
        float4 p1 = *reinterpret_cast<const float4*>(vbase + (size_t)((i + 1) & (Nc - 1)) * 64 + e0);
        float4 p2 = *reinterpret_cast<const float4*>(vbase + (size_t)((i + 2) & (Nc - 1)) * 64 + e0);
        float4 p3 = *reinterpret_cast<const float4*>(vbase + (size_t)((i + 3) & (Nc - 1)) * 64 + e0);

        float w0 = Ws[jr * 4 + 0], w1 = Ws[jr * 4 + 1];
        float w2 = Ws[jr * 4 + 2], w3 = Ws[jr * 4 + 3];

        float4 o;
        o.x = w0 * p0.x + w1 * p1.x + w2 * p2.x + w3 * p3.x;
        o.y = w0 * p0.y + w1 * p1.y + w2 * p2.y + w3 * p3.y;
        o.z = w0 * p0.z + w1 * p1.z + w2 * p2.z + w3 * p3.z;
        o.w = w0 * p0.w + w1 * p1.w + w2 * p2.w + w3 * p3.w;

        *reinterpret_cast<float4*>(&out[((size_t)b * Nc + i) * 64 + e0]) = o;
    }
}

extern "C" void kernel_launch(void* const* d_in, const int* in_sizes, int n_in,
                              void* d_out, int out_size)
{
    const float* X  = (const float*)d_in[0];   // (2, 8192, 64)
    const float* Wg = (const float*)d_in[1];   // (64, 64)
    const float* bg = (const float*)d_in[2];   // (64,)
    const float* Wf = (const float*)d_in[3];   // (3, 64, 8192)
    const float* bf = (const float*)d_in[4];   // (3, 8192)
    float* out = (float*)d_out;                // (2, 8192, 64)

    cudaFuncSetAttribute(smf_k1,
                         cudaFuncAttributeMaxDynamicSharedMemorySize, K1_SMEM_BYTES);

    smf_k1<<<256, 256, K1_SMEM_BYTES>>>(X, Wg, bg, Wf, bf);

    dim3 g2(Nc / 64, 2);                       // (128, 2)
    smf_k2<<<g2, 256>>>(out);
}